// round 14
// baseline (speedup 1.0000x reference)
#include <cuda_runtime.h>
#include <cuda_fp16.h>
#include <math.h>
#include <float.h>

// ---------------------------------------------------------------------------
// MLA forward, fp16 dataflow, fused epilogues, PDL.
// Pairwise-tile pipelines: one wait+barrier per TWO tiles (4-stage rings).
//   B=4, T=2048, C=768, H=12, D=64, R=64
// ---------------------------------------------------------------------------

#define BB 4
#define TT 2048
#define CC 768
#define HH 12
#define DD 64
#define RR 64
#define MROWS (BB * TT)            // 8192
#define KVW (2 * HH * DD)          // 1536
#define SCALE 0.125f
#define LOG2E 1.4426950408889634f

// Scratch (device globals)
__device__ __half g_xh  [MROWS * CC];
__device__ __half g_q16 [MROWS * CC];
__device__ __half g_ckvh[MROWS * RR];
__device__ __half g_kv16[MROWS * KVW];
__device__ __half g_ao16[MROWS * CC];
__device__ __half g_wq  [CC * HH * DD];
__device__ __half g_wdn [CC * RR];
__device__ __half g_wup [RR * KVW];
__device__ __half g_wo  [HH * DD * CC];
__device__ float2 g_rt  [TT * 32];       // rope cos/sin table

// ---------------------------------------------------------------------------
// helpers
// ---------------------------------------------------------------------------
__device__ __forceinline__ unsigned ph2(float lo, float hi) {
    __half2 h = __floats2half2_rn(lo, hi);
    return *(unsigned*)&h;
}

__device__ __forceinline__ unsigned ex2h2(unsigned x) {
    unsigned r;
    asm("ex2.approx.f16x2 %0, %1;" : "=r"(r) : "r"(x));
    return r;
}

__device__ __forceinline__ void mma16(float* c, const unsigned* a, unsigned b0, unsigned b1) {
    asm volatile(
        "mma.sync.aligned.m16n8k16.row.col.f32.f16.f16.f32 "
        "{%0,%1,%2,%3},{%4,%5,%6,%7},{%8,%9},{%0,%1,%2,%3};"
        : "+f"(c[0]), "+f"(c[1]), "+f"(c[2]), "+f"(c[3])
        : "r"(a[0]), "r"(a[1]), "r"(a[2]), "r"(a[3]), "r"(b0), "r"(b1));
}

__device__ __forceinline__ void ldsm4(unsigned* r, unsigned addr) {
    asm volatile("ldmatrix.sync.aligned.m8n8.x4.shared.b16 {%0,%1,%2,%3},[%4];"
                 : "=r"(r[0]), "=r"(r[1]), "=r"(r[2]), "=r"(r[3]) : "r"(addr));
}
__device__ __forceinline__ void ldsm4t(unsigned* r, unsigned addr) {
    asm volatile("ldmatrix.sync.aligned.m8n8.x4.trans.shared.b16 {%0,%1,%2,%3},[%4];"
                 : "=r"(r[0]), "=r"(r[1]), "=r"(r[2]), "=r"(r[3]) : "r"(addr));
}
__device__ __forceinline__ void ldsm2t(unsigned* r, unsigned addr) {
    asm volatile("ldmatrix.sync.aligned.m8n8.x2.trans.shared.b16 {%0,%1},[%2];"
                 : "=r"(r[0]), "=r"(r[1]) : "r"(addr));
}

__device__ __forceinline__ void cpa16(unsigned dst, const void* src) {
    asm volatile("cp.async.cg.shared.global [%0],[%1],16;" :: "r"(dst), "l"(src));
}
__device__ __forceinline__ void cpcommit() { asm volatile("cp.async.commit_group;"); }
__device__ __forceinline__ void cpwait0()  { asm volatile("cp.async.wait_group 0;"); }

__device__ __forceinline__ unsigned sptr(const void* p) {
    return (unsigned)__cvta_generic_to_shared(p);
}

// ---------------------------------------------------------------------------
// merged fp32->fp16 conversions + rope table (one launch)
// ---------------------------------------------------------------------------
__device__ __forceinline__ void conv8(const float* s, __half* d) {
    float4 v0 = *(const float4*)s;
    float4 v1 = *(const float4*)(s + 4);
    uint4 o = make_uint4(ph2(v0.x, v0.y), ph2(v0.z, v0.w),
                         ph2(v1.x, v1.y), ph2(v1.z, v1.w));
    *(uint4*)d = o;
}

#define C0 (MROWS * CC / 8)
#define C1 (C0 + CC * HH * DD / 8)
#define C2 (C1 + CC * RR / 8)
#define C3 (C2 + RR * KVW / 8)
#define C4 (C3 + HH * DD * CC / 8)
#define C5 (C4 + TT * 32)

__global__ __launch_bounds__(256) void f2h_all(
    const float* __restrict__ x,  const float* __restrict__ wq,
    const float* __restrict__ wdn,const float* __restrict__ wup,
    const float* __restrict__ wo,
    __half* __restrict__ xh, __half* __restrict__ hq, __half* __restrict__ hdn,
    __half* __restrict__ hup, __half* __restrict__ ho, float2* __restrict__ tab)
{
    int i = blockIdx.x * 256 + threadIdx.x;
    if      (i < C0) { int k = i * 8;            conv8(x + k,   xh + k); }
    else if (i < C1) { int k = (i - C0) * 8;     conv8(wq + k,  hq + k); }
    else if (i < C2) { int k = (i - C1) * 8;     conv8(wdn + k, hdn + k); }
    else if (i < C3) { int k = (i - C2) * 8;     conv8(wup + k, hup + k); }
    else if (i < C4) { int k = (i - C3) * 8;     conv8(wo + k,  ho + k); }
    else if (i < C5) {
        int k = i - C4;
        int d = k & 31, t = k >> 5;
        float inv = exp2f(-(float)d * (13.287712379549449f / 32.f));
        float sn, cs;
        sincosf((float)t * inv, &sn, &cs);
        tab[k] = make_float2(cs, sn);
    }
}

// ---------------------------------------------------------------------------
// GEMM core: 4-stage cp.async ring, pairwise k-iters (1 barrier per 2 iters).
//   EPI 1: fp32 out + bias; EPI 2: fp16 out + RoPE; EPI 3: fp16 out + LN(64)
// Requires (K>>5) even — true for K=768 (24) and K=64 (2).
// ---------------------------------------------------------------------------
template<int BN, int EPI, typename OutT>
__device__ __forceinline__ void gemm_core(char* smem,
    const __half* __restrict__ A, const __half* __restrict__ B,
    OutT* __restrict__ C, int M, int N, int K, int bx, int by,
    const float* __restrict__ bias,
    const float2* __restrict__ rt, float ropeScale, int ropeLimit,
    const float* __restrict__ lng, const float* __restrict__ lnb)
{
    constexpr int NT = BN / 16;
    constexpr int ASTR = 112;
    constexpr int BSTR = (BN == 128) ? 272 : 144;
    constexpr int ASTAGE = 128 * ASTR;
    constexpr int BSTAGE = 32 * BSTR;

    const unsigned uA = sptr(smem);
    const unsigned uB = uA + 4 * ASTAGE;

    const int tid  = threadIdx.x;
    const int lane = tid & 31;
    const int w    = tid >> 5;
    const int g    = lane >> 2;
    const int tig  = lane & 3;
    const int wm   = (w & 3) * 32;
    const int wn   = (w >> 2) * (BN / 2);
    const int m0   = by * 128;
    const int n0   = bx * BN;

    const int far = tid >> 1;
    const int fac = (tid & 1) * 2;
    const int fbk = tid >> 3;
    const int fbc = (BN == 128) ? (tid & 7) * 2 : (tid & 7);

    const __half* Asrc = A + (size_t)(m0 + far) * K + fac * 8;
    const __half* Bsrc = B + (size_t)fbk * N + n0 + fbc * 8;
    const unsigned adst = uA + far * ASTR + fac * 16;
    const unsigned bdst = uB + fbk * BSTR + fbc * 16;

    float acc[2][NT][4];
#pragma unroll
    for (int mt = 0; mt < 2; ++mt)
#pragma unroll
        for (int nt = 0; nt < NT; ++nt)
#pragma unroll
            for (int i = 0; i < 4; ++i) acc[mt][nt][i] = 0.f;

    const int niters = K >> 5;   // even

    // prologue: prefetch iters 0 and 1 into stages 0, 1
#pragma unroll
    for (int p = 0; p < 2; ++p) {
        const __half* as = Asrc + p * 32;
        const __half* bs = Bsrc + (size_t)p * 32 * N;
        cpa16(adst + p * ASTAGE, as); cpa16(adst + p * ASTAGE + 16, as + 8);
        cpa16(bdst + p * BSTAGE, bs);
        if (BN == 128) cpa16(bdst + p * BSTAGE + 16, bs + 8);
        cpcommit();
    }

    for (int it = 0; it < niters; it += 2) {
        cpwait0();
        __syncthreads();
        // prefetch it+2, it+3 (stages (it+2)&3, (it+3)&3; disjoint from reads)
#pragma unroll
        for (int p = 2; p < 4; ++p) {
            if (it + p < niters) {
                const int st = (it + p) & 3;
                const __half* as = Asrc + (it + p) * 32;
                const __half* bs = Bsrc + (size_t)(it + p) * 32 * N;
                cpa16(adst + st * ASTAGE, as); cpa16(adst + st * ASTAGE + 16, as + 8);
                cpa16(bdst + st * BSTAGE, bs);
                if (BN == 128) cpa16(bdst + st * BSTAGE + 16, bs + 8);
                cpcommit();
            }
        }

#pragma unroll
        for (int half = 0; half < 2; ++half) {
            const int st = (it + half) & 3;
            const unsigned aAb = uA + st * ASTAGE + (wm + (lane & 15)) * ASTR + ((lane >> 4) << 4);
            unsigned af[2][2][4];
#pragma unroll
            for (int kc = 0; kc < 2; ++kc)
#pragma unroll
                for (int mt = 0; mt < 2; ++mt)
                    ldsm4(af[kc][mt], aAb + mt * 16 * ASTR + kc * 32);

            const unsigned aBb = uB + st * BSTAGE + (lane & 15) * BSTR
                               + (wn + ((lane >> 4) << 3)) * 2;
#pragma unroll
            for (int kc = 0; kc < 2; ++kc) {
#pragma unroll
                for (int np = 0; np < NT / 2; ++np) {
                    unsigned bf[4];
                    ldsm4t(bf, aBb + kc * 16 * BSTR + np * 32);
                    mma16(acc[0][2 * np],     af[kc][0], bf[0], bf[1]);
                    mma16(acc[1][2 * np],     af[kc][1], bf[0], bf[1]);
                    mma16(acc[0][2 * np + 1], af[kc][0], bf[2], bf[3]);
                    mma16(acc[1][2 * np + 1], af[kc][1], bf[2], bf[3]);
                }
            }
        }
    }

    // ------------------------- epilogues -------------------------
    if constexpr (EPI == 1) {
#pragma unroll
        for (int mt = 0; mt < 2; ++mt) {
            const int r0 = m0 + wm + mt * 16 + g;
#pragma unroll
            for (int nt = 0; nt < NT; ++nt) {
                const int c0 = n0 + wn + nt * 8 + 2 * tig;
                const float b0 = bias[c0], b1 = bias[c0 + 1];
                *(float2*)((float*)C + (size_t)r0 * N + c0) =
                    make_float2(acc[mt][nt][0] + b0, acc[mt][nt][1] + b1);
                *(float2*)((float*)C + (size_t)(r0 + 8) * N + c0) =
                    make_float2(acc[mt][nt][2] + b0, acc[mt][nt][3] + b1);
            }
        }
    } else if constexpr (EPI == 2) {
        const bool doRope = (n0 + wn) < ropeLimit;
        __half* Ch = (__half*)C;
#pragma unroll
        for (int mt = 0; mt < 2; ++mt) {
            const int r0 = m0 + wm + mt * 16 + g;
            const int t0 = r0 & (TT - 1);
#pragma unroll
            for (int ntp = 0; ntp < 4; ++ntp) {
                const int clo = n0 + wn + ntp * 8 + 2 * tig;
                float lo0[2], hi0[2], lo1[2], hi1[2];
                if (doRope) {
#pragma unroll
                    for (int j = 0; j < 2; ++j) {
                        const int d = ntp * 8 + 2 * tig + j;
                        const float2 cs0 = rt[t0 * 32 + d];
                        const float2 cs1 = rt[(t0 + 8) * 32 + d];
                        const float xl0 = acc[mt][ntp][j],     xh0 = acc[mt][ntp + 4][j];
                        const float xl1 = acc[mt][ntp][j + 2], xh1 = acc[mt][ntp + 4][j + 2];
                        lo0[j] = xl0 * cs0.x - xh0 * cs0.y;
                        hi0[j] = xh0 * cs0.x + xl0 * cs0.y;
                        lo1[j] = xl1 * cs1.x - xh1 * cs1.y;
                        hi1[j] = xh1 * cs1.x + xl1 * cs1.y;
                    }
                } else {
#pragma unroll
                    for (int j = 0; j < 2; ++j) {
                        lo0[j] = acc[mt][ntp][j];     hi0[j] = acc[mt][ntp + 4][j];
                        lo1[j] = acc[mt][ntp][j + 2]; hi1[j] = acc[mt][ntp + 4][j + 2];
                    }
                }
                const float s = ropeScale;
                *(unsigned*)(Ch + (size_t)r0 * N + clo)        = ph2(lo0[0] * s, lo0[1] * s);
                *(unsigned*)(Ch + (size_t)r0 * N + clo + 32)   = ph2(hi0[0] * s, hi0[1] * s);
                *(unsigned*)(Ch + (size_t)(r0 + 8) * N + clo)      = ph2(lo1[0] * s, lo1[1] * s);
                *(unsigned*)(Ch + (size_t)(r0 + 8) * N + clo + 32) = ph2(hi1[0] * s, hi1[1] * s);
            }
        }
    } else if constexpr (EPI == 3) {
        __syncthreads();               // smem overlay: all ldsm of last pair done
        float2* red = (float2*)smem;
        float rs[2][2], rq[2][2];
#pragma unroll
        for (int mt = 0; mt < 2; ++mt)
#pragma unroll
            for (int hh = 0; hh < 2; ++hh) {
                float s = 0.f, sq = 0.f;
#pragma unroll
                for (int nt = 0; nt < NT; ++nt)
#pragma unroll
                    for (int j = 0; j < 2; ++j) {
                        float v = acc[mt][nt][2 * hh + j];
                        s += v; sq += v * v;
                    }
                s  += __shfl_xor_sync(0xffffffffu, s, 1);
                s  += __shfl_xor_sync(0xffffffffu, s, 2);
                sq += __shfl_xor_sync(0xffffffffu, sq, 1);
                sq += __shfl_xor_sync(0xffffffffu, sq, 2);
                rs[mt][hh] = s; rq[mt][hh] = sq;
            }
        if (tig == 0) {
#pragma unroll
            for (int mt = 0; mt < 2; ++mt)
#pragma unroll
                for (int hh = 0; hh < 2; ++hh) {
                    const int rl = wm + mt * 16 + g + hh * 8;
                    red[(w >> 2) * 128 + rl] = make_float2(rs[mt][hh], rq[mt][hh]);
                }
        }
        __syncthreads();
        __half* Ch = (__half*)C;
#pragma unroll
        for (int mt = 0; mt < 2; ++mt)
#pragma unroll
            for (int hh = 0; hh < 2; ++hh) {
                const int rl = wm + mt * 16 + g + hh * 8;
                const float2 a = red[rl], bb = red[128 + rl];
                const float mean = (a.x + bb.x) * (1.f / 64.f);
                const float var  = (a.y + bb.y) * (1.f / 64.f) - mean * mean;
                const float inv  = rsqrtf(var + 1e-5f);
                const int r0 = m0 + rl;
#pragma unroll
                for (int nt = 0; nt < NT; ++nt) {
                    const int c = wn + nt * 8 + 2 * tig;
                    const float v0 = (acc[mt][nt][2 * hh]     - mean) * inv * lng[c]     + lnb[c];
                    const float v1 = (acc[mt][nt][2 * hh + 1] - mean) * inv * lng[c + 1] + lnb[c + 1];
                    *(unsigned*)(Ch + (size_t)r0 * N + c) = ph2(v0, v1);
                }
            }
    }
}

// standalone GEMM wrapper
template<int BN, int EPI, typename OutT>
__global__ __launch_bounds__(256) void hgemm16(
    const __half* __restrict__ A, const __half* __restrict__ B,
    OutT* __restrict__ C, int M, int N, int K,
    const float* __restrict__ bias,
    const float2* __restrict__ rt, float ropeScale, int ropeLimit,
    const float* __restrict__ lng, const float* __restrict__ lnb)
{
    extern __shared__ __align__(16) char sm[];
    gemm_core<BN, EPI, OutT>(sm, A, B, C, M, N, K, blockIdx.x, blockIdx.y,
                             bias, rt, ropeScale, ropeLimit, lng, lnb);
}

// fused Wq (RoPE) + Wdown (LayerNorm): gridDim.x = 7
__global__ __launch_bounds__(256) void qdown_k(
    const __half* __restrict__ xh, const __half* __restrict__ wq,
    const __half* __restrict__ wdn, __half* __restrict__ q16,
    __half* __restrict__ ckvh, const float2* __restrict__ rt, float qscale,
    const float* __restrict__ lng, const float* __restrict__ lnb)
{
    extern __shared__ __align__(16) char sm[];
    if (blockIdx.x < 6)
        gemm_core<128, 2, __half>(sm, xh, wq, q16, MROWS, CC, CC,
                                  blockIdx.x, blockIdx.y,
                                  nullptr, rt, qscale, CC, nullptr, nullptr);
    else
        gemm_core<64, 3, __half>(sm, xh, wdn, ckvh, MROWS, RR, CC,
                                 0, blockIdx.y,
                                 nullptr, nullptr, 0.f, 0, lng, lnb);
}

#define GEMM_SMEM (4 * 128 * 112 + 4 * 32 * 272)   // 92160

// ---------------------------------------------------------------------------
// Causal flash attention: 256 threads, 8 warps x 16 q-rows.
// 4-stage KV ring, pairwise tiles: one wait+barrier per TWO tiles.
// l via MMA on all-ones V pad, fp16x2 exp. ntile = 2qi+2 (always even).
// ---------------------------------------------------------------------------
#define KVBYTES (64 * 144)
#define QBYTES  (128 * 144)
#define NSTG    4
#define ASMEM   (QBYTES + 2 * NSTG * KVBYTES)   // 92160

__global__ __launch_bounds__(256, 2) void attn_f16(
    const __half* __restrict__ q, const __half* __restrict__ kv, __half* __restrict__ ao)
{
    extern __shared__ __align__(16) char sm[];
    const unsigned uQ = sptr(sm);
    const unsigned uK = uQ + QBYTES;
    const unsigned uV = uK + NSTG * KVBYTES;

    const int tid  = threadIdx.x;
    const int lane = tid & 31;
    const int w    = tid >> 5;
    const int g    = lane >> 2;
    const int tig  = lane & 3;
    const int qi   = (gridDim.x - 1) - blockIdx.x;
    const int i0   = qi * 128;
    const int h    = blockIdx.y;
    const int b    = blockIdx.z;
    const int rb   = w * 16;
    const int row_min = i0 + rb;
    const int row_max = row_min + 15;

    // Q fill (warp-local rows)
    {
        const int r  = tid >> 1;
        const int hh = (tid & 1) * 32;
        const uint4* src = (const uint4*)(q + (size_t)(b * TT + i0 + r) * CC + h * DD + hh);
        char* dst = sm + r * 144 + hh * 2;
        uint4 v0 = src[0], v1 = src[1], v2 = src[2], v3 = src[3];
        *(uint4*)dst = v0; *(uint4*)(dst + 16) = v1;
        *(uint4*)(dst + 32) = v2; *(uint4*)(dst + 48) = v3;
    }
    // V pad columns = 1.0h in all NSTG stages (cp.async never writes 128..143)
    {
        const int stg = tid >> 6;        // 0..3  (NSTG*64 == 256 == blockDim)
        const int r   = tid & 63;
        *(uint4*)(sm + QBYTES + (NSTG + stg) * KVBYTES + r * 144 + 128) =
            make_uint4(0x3C003C00u, 0x3C003C00u, 0x3C003C00u, 0x3C003C00u);
    }
    __syncwarp();

    unsigned qa[4][4];
    {
        const unsigned aQ = uQ + (rb + (lane & 15)) * 144 + ((lane >> 4) << 4);
#pragma unroll
        for (int kc = 0; kc < 4; ++kc) ldsm4(qa[kc], aQ + kc * 32);
    }

    // KV prefetch mapping
    const int fr = tid >> 2;
    const int fc = (tid & 3) * 2;
    const size_t kvrow0 = (size_t)(b * TT) * KVW + h * DD + fc * 8;

    const int ntile = 2 * qi + 2;        // even
    // prologue: prefetch tiles 0, 1 into stages 0, 1
#pragma unroll
    for (int p = 0; p < 2; ++p) {
        const __half* ks = kv + kvrow0 + (size_t)(p * 64 + fr) * KVW;
        const unsigned kd = uK + p * KVBYTES + fr * 144 + fc * 16;
        cpa16(kd, ks); cpa16(kd + 16, ks + 8);
        const unsigned vd = uV + p * KVBYTES + fr * 144 + fc * 16;
        cpa16(vd, ks + HH * DD); cpa16(vd + 16, ks + HH * DD + 8);
        cpcommit();
    }

    float mr0 = -INFINITY, mr1 = -INFINITY;
    float oacc[8][4], osum[4];
#pragma unroll
    for (int nt = 0; nt < 8; ++nt)
#pragma unroll
        for (int i = 0; i < 4; ++i) oacc[nt][i] = 0.f;
#pragma unroll
    for (int i = 0; i < 4; ++i) osum[i] = 0.f;

    for (int jp = 0; jp < ntile; jp += 2) {
        cpwait0();            // tiles jp, jp+1 resident
        __syncthreads();      // all reads of stages (jp-2),(jp-1) done
        // prefetch jp+2, jp+3 into stages (jp+2)&3, (jp+3)&3 (disjoint from jp,jp+1)
#pragma unroll
        for (int p = 2; p < 4; ++p) {
            if (jp + p < ntile) {
                const int st = (jp + p) & 3;
                const __half* ks = kv + kvrow0 + (size_t)((jp + p) * 64 + fr) * KVW;
                const unsigned kd = uK + st * KVBYTES + fr * 144 + fc * 16;
                cpa16(kd, ks); cpa16(kd + 16, ks + 8);
                const unsigned vd = uV + st * KVBYTES + fr * 144 + fc * 16;
                cpa16(vd, ks + HH * DD); cpa16(vd + 16, ks + HH * DD + 8);
                cpcommit();
            }
        }

#pragma unroll
        for (int half = 0; half < 2; ++half) {
            const int jt = jp + half;
            const int j0 = jt * 64;
            if (j0 > row_max) continue;
            const int cst = jt & 3;

            // --- S = Q K^T ---
            float sacc[8][4];
#pragma unroll
            for (int nt = 0; nt < 8; ++nt)
#pragma unroll
                for (int i = 0; i < 4; ++i) sacc[nt][i] = 0.f;

            const unsigned aK = uK + cst * KVBYTES
                              + ((lane & 7) + ((lane & 16) >> 1)) * 144 + ((lane & 8) << 1);
#pragma unroll
            for (int kc = 0; kc < 4; ++kc) {
#pragma unroll
                for (int np = 0; np < 4; ++np) {
                    unsigned bf[4];
                    ldsm4(bf, aK + np * 16 * 144 + kc * 32);
                    mma16(sacc[2 * np],     qa[kc], bf[0], bf[1]);
                    mma16(sacc[2 * np + 1], qa[kc], bf[2], bf[3]);
                }
            }

            // --- causal mask (partial tile only) ---
            if (j0 + 63 > row_min) {
                const int r0g = row_min + g, r1g = r0g + 8;
#pragma unroll
                for (int nt = 0; nt < 8; ++nt) {
                    const int c = j0 + nt * 8 + 2 * tig;
                    if (c > r0g)     sacc[nt][0] = -INFINITY;
                    if (c + 1 > r0g) sacc[nt][1] = -INFINITY;
                    if (c > r1g)     sacc[nt][2] = -INFINITY;
                    if (c + 1 > r1g) sacc[nt][3] = -INFINITY;
                }
            }

            // --- online softmax (base 2) ---
            float tm0 = -INFINITY, tm1 = -INFINITY;
#pragma unroll
            for (int nt = 0; nt < 8; ++nt) {
                tm0 = fmaxf(tm0, fmaxf(sacc[nt][0], sacc[nt][1]));
                tm1 = fmaxf(tm1, fmaxf(sacc[nt][2], sacc[nt][3]));
            }
            tm0 = fmaxf(tm0, __shfl_xor_sync(0xffffffffu, tm0, 1));
            tm0 = fmaxf(tm0, __shfl_xor_sync(0xffffffffu, tm0, 2));
            tm1 = fmaxf(tm1, __shfl_xor_sync(0xffffffffu, tm1, 1));
            tm1 = fmaxf(tm1, __shfl_xor_sync(0xffffffffu, tm1, 2));

            const float mn0 = fmaxf(mr0, tm0), mn1 = fmaxf(mr1, tm1);
            const float al0 = exp2f(mr0 - mn0), al1 = exp2f(mr1 - mn1);
            mr0 = mn0; mr1 = mn1;

            unsigned pfr[4][4];
#pragma unroll
            for (int kk = 0; kk < 4; ++kk) {
                pfr[kk][0] = ex2h2(ph2(sacc[2 * kk][0] - mn0,     sacc[2 * kk][1] - mn0));
                pfr[kk][1] = ex2h2(ph2(sacc[2 * kk][2] - mn1,     sacc[2 * kk][3] - mn1));
                pfr[kk][2] = ex2h2(ph2(sacc[2 * kk + 1][0] - mn0, sacc[2 * kk + 1][1] - mn0));
                pfr[kk][3] = ex2h2(ph2(sacc[2 * kk + 1][2] - mn1, sacc[2 * kk + 1][3] - mn1));
            }

#pragma unroll
            for (int nt = 0; nt < 8; ++nt) {
                oacc[nt][0] *= al0; oacc[nt][1] *= al0;
                oacc[nt][2] *= al1; oacc[nt][3] *= al1;
            }
            osum[0] *= al0; osum[1] *= al0;
            osum[2] *= al1; osum[3] *= al1;

            // --- O += P V ; l += P 1 (pad column) ---
            const unsigned aV  = uV + cst * KVBYTES + (lane & 15) * 144 + (lane & 16);
            const unsigned aVs = uV + cst * KVBYTES + (lane & 15) * 144 + 128;
#pragma unroll
            for (int kc = 0; kc < 4; ++kc) {
#pragma unroll
                for (int np = 0; np < 4; ++np) {
                    unsigned bf[4];
                    ldsm4t(bf, aV + kc * 16 * 144 + np * 32);
                    mma16(oacc[2 * np],     pfr[kc], bf[0], bf[1]);
                    mma16(oacc[2 * np + 1], pfr[kc], bf[2], bf[3]);
                }
                unsigned bl[2];
                ldsm2t(bl, aVs + kc * 16 * 144);
                mma16(osum, pfr[kc], bl[0], bl[1]);
            }
        }
    }

    const float inv0 = 1.f / osum[0], inv1 = 1.f / osum[2];
    __half* dst0 = ao + (size_t)(b * TT + i0 + rb + g) * CC + h * DD;
    __half* dst1 = dst0 + (size_t)8 * CC;
#pragma unroll
    for (int nt = 0; nt < 8; ++nt) {
        const int c = nt * 8 + 2 * tig;
        *(unsigned*)(dst0 + c) = ph2(oacc[nt][0] * inv0, oacc[nt][1] * inv0);
        *(unsigned*)(dst1 + c) = ph2(oacc[nt][2] * inv1, oacc[nt][3] * inv1);
    }
}

// ---------------------------------------------------------------------------
// Launch (PDL on dependent kernels)
// ---------------------------------------------------------------------------
extern "C" void kernel_launch(void* const* d_in, const int* in_sizes, int n_in,
                              void* d_out, int out_size)
{
    const float* x     = (const float*)d_in[0];
    const float* Wq    = (const float*)d_in[1];
    const float* Wdown = (const float*)d_in[2];
    const float* ln_g  = (const float*)d_in[3];
    const float* ln_b  = (const float*)d_in[4];
    const float* Wup   = (const float*)d_in[5];
    const float* Wo    = (const float*)d_in[6];
    const float* bo    = (const float*)d_in[7];
    float* out = (float*)d_out;

    void *pxh, *pq, *pckvh, *pkv, *pao, *pwq, *pwdn, *pwup, *pwo, *prt;
    cudaGetSymbolAddress(&pxh,  g_xh);
    cudaGetSymbolAddress(&pq,   g_q16);
    cudaGetSymbolAddress(&pckvh,g_ckvh);
    cudaGetSymbolAddress(&pkv,  g_kv16);
    cudaGetSymbolAddress(&pao,  g_ao16);
    cudaGetSymbolAddress(&pwq,  g_wq);
    cudaGetSymbolAddress(&pwdn, g_wdn);
    cudaGetSymbolAddress(&pwup, g_wup);
    cudaGetSymbolAddress(&pwo,  g_wo);
    cudaGetSymbolAddress(&prt,  g_rt);
    __half* xh   = (__half*)pxh;
    __half* q16  = (__half*)pq;
    __half* ckvh = (__half*)pckvh;
    __half* kv16 = (__half*)pkv;
    __half* ao16 = (__half*)pao;
    __half* wq   = (__half*)pwq;
    __half* wdn  = (__half*)pwdn;
    __half* wup  = (__half*)pwup;
    __half* wo   = (__half*)pwo;
    float2* rt   = (float2*)prt;

    cudaFuncSetAttribute(attn_f16, cudaFuncAttributeMaxDynamicSharedMemorySize, ASMEM);
    cudaFuncSetAttribute(qdown_k,  cudaFuncAttributeMaxDynamicSharedMemorySize, GEMM_SMEM);
    cudaFuncSetAttribute(hgemm16<128, 2, __half>,
                         cudaFuncAttributeMaxDynamicSharedMemorySize, GEMM_SMEM);
    cudaFuncSetAttribute(hgemm16<128, 1, float>,
                         cudaFuncAttributeMaxDynamicSharedMemorySize, GEMM_SMEM);

    cudaLaunchAttribute pdl[1];
    pdl[0].id = cudaLaunchAttributeProgrammaticStreamSerialization;
    pdl[0].val.programmaticStreamSerializationAllowed = 1;

    // 0) conversions + rope table
    f2h_all<<<C5 / 256, 256>>>(x, Wq, Wdown, Wup, Wo, xh, wq, wdn, wup, wo, rt);

    // 1) fused: q = rope(x@Wq)*SCALE*log2e  AND  ckv = layernorm(x@Wdown)
    {
        cudaLaunchConfig_t cfg = {};
        cfg.gridDim = dim3(7, MROWS / 128); cfg.blockDim = dim3(256);
        cfg.dynamicSmemBytes = GEMM_SMEM;
        cfg.attrs = pdl; cfg.numAttrs = 1;
        float qscale = SCALE * LOG2E;
        cudaLaunchKernelEx(&cfg, qdown_k,
            (const __half*)xh, (const __half*)wq, (const __half*)wdn,
            q16, ckvh, (const float2*)rt, qscale, ln_g, ln_b);
    }

    // 2) kv = ckv @ Wup, rope on K half
    {
        cudaLaunchConfig_t cfg = {};
        cfg.gridDim = dim3(KVW / 128, MROWS / 128); cfg.blockDim = dim3(256);
        cfg.dynamicSmemBytes = GEMM_SMEM;
        cfg.attrs = pdl; cfg.numAttrs = 1;
        float one = 1.0f; int lim = HH * DD;
        cudaLaunchKernelEx(&cfg, hgemm16<128, 2, __half>,
            (const __half*)ckvh, (const __half*)wup, kv16,
            (int)MROWS, (int)KVW, (int)RR,
            (const float*)nullptr, (const float2*)rt, one, lim,
            (const float*)nullptr, (const float*)nullptr);
    }

    // 3) attention (4-stage ring, pairwise tiles)
    {
        cudaLaunchConfig_t cfg = {};
        cfg.gridDim = dim3(TT / 128, HH, BB); cfg.blockDim = dim3(256);
        cfg.dynamicSmemBytes = ASMEM;
        cfg.attrs = pdl; cfg.numAttrs = 1;
        cudaLaunchKernelEx(&cfg, attn_f16,
            (const __half*)q16, (const __half*)kv16, ao16);
    }

    // 4) out = ao @ Wo + bo
    {
        cudaLaunchConfig_t cfg = {};
        cfg.gridDim = dim3(CC / 128, MROWS / 128); cfg.blockDim = dim3(256);
        cfg.dynamicSmemBytes = GEMM_SMEM;
        cfg.attrs = pdl; cfg.numAttrs = 1;
        float zero = 0.f; int zlim = 0;
        cudaLaunchKernelEx(&cfg, hgemm16<128, 1, float>,
            (const __half*)ao16, (const __half*)wo, out,
            (int)MROWS, (int)CC, (int)CC,
            bo, (const float2*)nullptr, zero, zlim,
            (const float*)nullptr, (const float*)nullptr);
    }
}

// round 15
// speedup vs baseline: 1.0825x; 1.0825x over previous
#include <cuda_runtime.h>
#include <cuda_fp16.h>
#include <math.h>
#include <float.h>

// ---------------------------------------------------------------------------
// MLA forward, fp16 dataflow, fused epilogues, PDL.
// GEMMs: 2-stage, 1 barrier/iter (4 CTAs/SM). Attention: 5-stage KV ring,
// prefetch-first, 1 barrier/tile, cpwait2 slack (2 CTAs/SM).
//   B=4, T=2048, C=768, H=12, D=64, R=64
// ---------------------------------------------------------------------------

#define BB 4
#define TT 2048
#define CC 768
#define HH 12
#define DD 64
#define RR 64
#define MROWS (BB * TT)            // 8192
#define KVW (2 * HH * DD)          // 1536
#define SCALE 0.125f
#define LOG2E 1.4426950408889634f

// Scratch (device globals)
__device__ __half g_xh  [MROWS * CC];
__device__ __half g_q16 [MROWS * CC];
__device__ __half g_ckvh[MROWS * RR];
__device__ __half g_kv16[MROWS * KVW];
__device__ __half g_ao16[MROWS * CC];
__device__ __half g_wq  [CC * HH * DD];
__device__ __half g_wdn [CC * RR];
__device__ __half g_wup [RR * KVW];
__device__ __half g_wo  [HH * DD * CC];
__device__ float2 g_rt  [TT * 32];       // rope cos/sin table

// ---------------------------------------------------------------------------
// helpers
// ---------------------------------------------------------------------------
__device__ __forceinline__ unsigned ph2(float lo, float hi) {
    __half2 h = __floats2half2_rn(lo, hi);
    return *(unsigned*)&h;
}

__device__ __forceinline__ unsigned ex2h2(unsigned x) {
    unsigned r;
    asm("ex2.approx.f16x2 %0, %1;" : "=r"(r) : "r"(x));
    return r;
}

__device__ __forceinline__ void mma16(float* c, const unsigned* a, unsigned b0, unsigned b1) {
    asm volatile(
        "mma.sync.aligned.m16n8k16.row.col.f32.f16.f16.f32 "
        "{%0,%1,%2,%3},{%4,%5,%6,%7},{%8,%9},{%0,%1,%2,%3};"
        : "+f"(c[0]), "+f"(c[1]), "+f"(c[2]), "+f"(c[3])
        : "r"(a[0]), "r"(a[1]), "r"(a[2]), "r"(a[3]), "r"(b0), "r"(b1));
}

__device__ __forceinline__ void ldsm4(unsigned* r, unsigned addr) {
    asm volatile("ldmatrix.sync.aligned.m8n8.x4.shared.b16 {%0,%1,%2,%3},[%4];"
                 : "=r"(r[0]), "=r"(r[1]), "=r"(r[2]), "=r"(r[3]) : "r"(addr));
}
__device__ __forceinline__ void ldsm4t(unsigned* r, unsigned addr) {
    asm volatile("ldmatrix.sync.aligned.m8n8.x4.trans.shared.b16 {%0,%1,%2,%3},[%4];"
                 : "=r"(r[0]), "=r"(r[1]), "=r"(r[2]), "=r"(r[3]) : "r"(addr));
}
__device__ __forceinline__ void ldsm2t(unsigned* r, unsigned addr) {
    asm volatile("ldmatrix.sync.aligned.m8n8.x2.trans.shared.b16 {%0,%1},[%2];"
                 : "=r"(r[0]), "=r"(r[1]) : "r"(addr));
}

__device__ __forceinline__ void cpa16(unsigned dst, const void* src) {
    asm volatile("cp.async.cg.shared.global [%0],[%1],16;" :: "r"(dst), "l"(src));
}
__device__ __forceinline__ void cpcommit() { asm volatile("cp.async.commit_group;"); }
__device__ __forceinline__ void cpwait0()  { asm volatile("cp.async.wait_group 0;"); }
__device__ __forceinline__ void cpwait1()  { asm volatile("cp.async.wait_group 1;"); }
__device__ __forceinline__ void cpwait2()  { asm volatile("cp.async.wait_group 2;"); }

__device__ __forceinline__ unsigned sptr(const void* p) {
    return (unsigned)__cvta_generic_to_shared(p);
}

// ---------------------------------------------------------------------------
// merged fp32->fp16 conversions + rope table (one launch)
// ---------------------------------------------------------------------------
__device__ __forceinline__ void conv8(const float* s, __half* d) {
    float4 v0 = *(const float4*)s;
    float4 v1 = *(const float4*)(s + 4);
    uint4 o = make_uint4(ph2(v0.x, v0.y), ph2(v0.z, v0.w),
                         ph2(v1.x, v1.y), ph2(v1.z, v1.w));
    *(uint4*)d = o;
}

#define C0 (MROWS * CC / 8)
#define C1 (C0 + CC * HH * DD / 8)
#define C2 (C1 + CC * RR / 8)
#define C3 (C2 + RR * KVW / 8)
#define C4 (C3 + HH * DD * CC / 8)
#define C5 (C4 + TT * 32)

__global__ __launch_bounds__(256) void f2h_all(
    const float* __restrict__ x,  const float* __restrict__ wq,
    const float* __restrict__ wdn,const float* __restrict__ wup,
    const float* __restrict__ wo,
    __half* __restrict__ xh, __half* __restrict__ hq, __half* __restrict__ hdn,
    __half* __restrict__ hup, __half* __restrict__ ho, float2* __restrict__ tab)
{
    int i = blockIdx.x * 256 + threadIdx.x;
    if      (i < C0) { int k = i * 8;            conv8(x + k,   xh + k); }
    else if (i < C1) { int k = (i - C0) * 8;     conv8(wq + k,  hq + k); }
    else if (i < C2) { int k = (i - C1) * 8;     conv8(wdn + k, hdn + k); }
    else if (i < C3) { int k = (i - C2) * 8;     conv8(wup + k, hup + k); }
    else if (i < C4) { int k = (i - C3) * 8;     conv8(wo + k,  ho + k); }
    else if (i < C5) {
        int k = i - C4;
        int d = k & 31, t = k >> 5;
        float inv = exp2f(-(float)d * (13.287712379549449f / 32.f));
        float sn, cs;
        sincosf((float)t * inv, &sn, &cs);
        tab[k] = make_float2(cs, sn);
    }
}

// ---------------------------------------------------------------------------
// GEMM core (2-stage cp.async, ONE barrier per k-iter: wait/bar/prefetch/mma).
//   EPI 1: fp32 out + bias; EPI 2: fp16 out + RoPE; EPI 3: fp16 out + LN(64)
// ---------------------------------------------------------------------------
template<int BN, int EPI, typename OutT>
__device__ __forceinline__ void gemm_core(char* smem,
    const __half* __restrict__ A, const __half* __restrict__ B,
    OutT* __restrict__ C, int M, int N, int K, int bx, int by,
    const float* __restrict__ bias,
    const float2* __restrict__ rt, float ropeScale, int ropeLimit,
    const float* __restrict__ lng, const float* __restrict__ lnb)
{
    constexpr int NT = BN / 16;
    constexpr int ASTR = 112;
    constexpr int BSTR = (BN == 128) ? 272 : 144;
    constexpr int ASTAGE = 128 * ASTR;
    constexpr int BSTAGE = 32 * BSTR;

    const unsigned uA = sptr(smem);
    const unsigned uB = uA + 2 * ASTAGE;

    const int tid  = threadIdx.x;
    const int lane = tid & 31;
    const int w    = tid >> 5;
    const int g    = lane >> 2;
    const int tig  = lane & 3;
    const int wm   = (w & 3) * 32;
    const int wn   = (w >> 2) * (BN / 2);
    const int m0   = by * 128;
    const int n0   = bx * BN;

    const int far = tid >> 1;
    const int fac = (tid & 1) * 2;
    const int fbk = tid >> 3;
    const int fbc = (BN == 128) ? (tid & 7) * 2 : (tid & 7);

    const __half* Asrc = A + (size_t)(m0 + far) * K + fac * 8;
    const __half* Bsrc = B + (size_t)fbk * N + n0 + fbc * 8;
    const unsigned adst = uA + far * ASTR + fac * 16;
    const unsigned bdst = uB + fbk * BSTR + fbc * 16;

    float acc[2][NT][4];
#pragma unroll
    for (int mt = 0; mt < 2; ++mt)
#pragma unroll
        for (int nt = 0; nt < NT; ++nt)
#pragma unroll
            for (int i = 0; i < 4; ++i) acc[mt][nt][i] = 0.f;

    const int niters = K >> 5;

    // prologue: prefetch tile 0
    cpa16(adst, Asrc); cpa16(adst + 16, Asrc + 8);
    cpa16(bdst, Bsrc);
    if (BN == 128) cpa16(bdst + 16, Bsrc + 8);
    cpcommit();

    for (int it = 0; it < niters; ++it) {
        cpwait0();
        __syncthreads();
        if (it + 1 < niters) {
            const int st = (it + 1) & 1;
            const __half* as = Asrc + (it + 1) * 32;
            const __half* bs = Bsrc + (size_t)(it + 1) * 32 * N;
            cpa16(adst + st * ASTAGE, as); cpa16(adst + st * ASTAGE + 16, as + 8);
            cpa16(bdst + st * BSTAGE, bs);
            if (BN == 128) cpa16(bdst + st * BSTAGE + 16, bs + 8);
            cpcommit();
        }

        const int st = it & 1;
        const unsigned aAb = uA + st * ASTAGE + (wm + (lane & 15)) * ASTR + ((lane >> 4) << 4);
        unsigned af[2][2][4];
#pragma unroll
        for (int kc = 0; kc < 2; ++kc)
#pragma unroll
            for (int mt = 0; mt < 2; ++mt)
                ldsm4(af[kc][mt], aAb + mt * 16 * ASTR + kc * 32);

        const unsigned aBb = uB + st * BSTAGE + (lane & 15) * BSTR
                           + (wn + ((lane >> 4) << 3)) * 2;
#pragma unroll
        for (int kc = 0; kc < 2; ++kc) {
#pragma unroll
            for (int np = 0; np < NT / 2; ++np) {
                unsigned bf[4];
                ldsm4t(bf, aBb + kc * 16 * BSTR + np * 32);
                mma16(acc[0][2 * np],     af[kc][0], bf[0], bf[1]);
                mma16(acc[1][2 * np],     af[kc][1], bf[0], bf[1]);
                mma16(acc[0][2 * np + 1], af[kc][0], bf[2], bf[3]);
                mma16(acc[1][2 * np + 1], af[kc][1], bf[2], bf[3]);
            }
        }
    }

    // ------------------------- epilogues -------------------------
    if constexpr (EPI == 1) {
#pragma unroll
        for (int mt = 0; mt < 2; ++mt) {
            const int r0 = m0 + wm + mt * 16 + g;
#pragma unroll
            for (int nt = 0; nt < NT; ++nt) {
                const int c0 = n0 + wn + nt * 8 + 2 * tig;
                const float b0 = bias[c0], b1 = bias[c0 + 1];
                *(float2*)((float*)C + (size_t)r0 * N + c0) =
                    make_float2(acc[mt][nt][0] + b0, acc[mt][nt][1] + b1);
                *(float2*)((float*)C + (size_t)(r0 + 8) * N + c0) =
                    make_float2(acc[mt][nt][2] + b0, acc[mt][nt][3] + b1);
            }
        }
    } else if constexpr (EPI == 2) {
        const bool doRope = (n0 + wn) < ropeLimit;
        __half* Ch = (__half*)C;
#pragma unroll
        for (int mt = 0; mt < 2; ++mt) {
            const int r0 = m0 + wm + mt * 16 + g;
            const int t0 = r0 & (TT - 1);
#pragma unroll
            for (int ntp = 0; ntp < 4; ++ntp) {
                const int clo = n0 + wn + ntp * 8 + 2 * tig;
                float lo0[2], hi0[2], lo1[2], hi1[2];
                if (doRope) {
#pragma unroll
                    for (int j = 0; j < 2; ++j) {
                        const int d = ntp * 8 + 2 * tig + j;
                        const float2 cs0 = rt[t0 * 32 + d];
                        const float2 cs1 = rt[(t0 + 8) * 32 + d];
                        const float xl0 = acc[mt][ntp][j],     xh0 = acc[mt][ntp + 4][j];
                        const float xl1 = acc[mt][ntp][j + 2], xh1 = acc[mt][ntp + 4][j + 2];
                        lo0[j] = xl0 * cs0.x - xh0 * cs0.y;
                        hi0[j] = xh0 * cs0.x + xl0 * cs0.y;
                        lo1[j] = xl1 * cs1.x - xh1 * cs1.y;
                        hi1[j] = xh1 * cs1.x + xl1 * cs1.y;
                    }
                } else {
#pragma unroll
                    for (int j = 0; j < 2; ++j) {
                        lo0[j] = acc[mt][ntp][j];     hi0[j] = acc[mt][ntp + 4][j];
                        lo1[j] = acc[mt][ntp][j + 2]; hi1[j] = acc[mt][ntp + 4][j + 2];
                    }
                }
                const float s = ropeScale;
                *(unsigned*)(Ch + (size_t)r0 * N + clo)        = ph2(lo0[0] * s, lo0[1] * s);
                *(unsigned*)(Ch + (size_t)r0 * N + clo + 32)   = ph2(hi0[0] * s, hi0[1] * s);
                *(unsigned*)(Ch + (size_t)(r0 + 8) * N + clo)      = ph2(lo1[0] * s, lo1[1] * s);
                *(unsigned*)(Ch + (size_t)(r0 + 8) * N + clo + 32) = ph2(hi1[0] * s, hi1[1] * s);
            }
        }
    } else if constexpr (EPI == 3) {
        __syncthreads();               // smem overlay: all ldsm of last tile done
        float2* red = (float2*)smem;
        float rs[2][2], rq[2][2];
#pragma unroll
        for (int mt = 0; mt < 2; ++mt)
#pragma unroll
            for (int hh = 0; hh < 2; ++hh) {
                float s = 0.f, sq = 0.f;
#pragma unroll
                for (int nt = 0; nt < NT; ++nt)
#pragma unroll
                    for (int j = 0; j < 2; ++j) {
                        float v = acc[mt][nt][2 * hh + j];
                        s += v; sq += v * v;
                    }
                s  += __shfl_xor_sync(0xffffffffu, s, 1);
                s  += __shfl_xor_sync(0xffffffffu, s, 2);
                sq += __shfl_xor_sync(0xffffffffu, sq, 1);
                sq += __shfl_xor_sync(0xffffffffu, sq, 2);
                rs[mt][hh] = s; rq[mt][hh] = sq;
            }
        if (tig == 0) {
#pragma unroll
            for (int mt = 0; mt < 2; ++mt)
#pragma unroll
                for (int hh = 0; hh < 2; ++hh) {
                    const int rl = wm + mt * 16 + g + hh * 8;
                    red[(w >> 2) * 128 + rl] = make_float2(rs[mt][hh], rq[mt][hh]);
                }
        }
        __syncthreads();
        __half* Ch = (__half*)C;
#pragma unroll
        for (int mt = 0; mt < 2; ++mt)
#pragma unroll
            for (int hh = 0; hh < 2; ++hh) {
                const int rl = wm + mt * 16 + g + hh * 8;
                const float2 a = red[rl], bb = red[128 + rl];
                const float mean = (a.x + bb.x) * (1.f / 64.f);
                const float var  = (a.y + bb.y) * (1.f / 64.f) - mean * mean;
                const float inv  = rsqrtf(var + 1e-5f);
                const int r0 = m0 + rl;
#pragma unroll
                for (int nt = 0; nt < NT; ++nt) {
                    const int c = wn + nt * 8 + 2 * tig;
                    const float v0 = (acc[mt][nt][2 * hh]     - mean) * inv * lng[c]     + lnb[c];
                    const float v1 = (acc[mt][nt][2 * hh + 1] - mean) * inv * lng[c + 1] + lnb[c + 1];
                    *(unsigned*)(Ch + (size_t)r0 * N + c) = ph2(v0, v1);
                }
            }
    }
}

// standalone GEMM wrapper
template<int BN, int EPI, typename OutT>
__global__ __launch_bounds__(256) void hgemm16(
    const __half* __restrict__ A, const __half* __restrict__ B,
    OutT* __restrict__ C, int M, int N, int K,
    const float* __restrict__ bias,
    const float2* __restrict__ rt, float ropeScale, int ropeLimit,
    const float* __restrict__ lng, const float* __restrict__ lnb)
{
    extern __shared__ __align__(16) char sm[];
    gemm_core<BN, EPI, OutT>(sm, A, B, C, M, N, K, blockIdx.x, blockIdx.y,
                             bias, rt, ropeScale, ropeLimit, lng, lnb);
}

// fused Wq (RoPE) + Wdown (LayerNorm): gridDim.x = 7
__global__ __launch_bounds__(256) void qdown_k(
    const __half* __restrict__ xh, const __half* __restrict__ wq,
    const __half* __restrict__ wdn, __half* __restrict__ q16,
    __half* __restrict__ ckvh, const float2* __restrict__ rt, float qscale,
    const float* __restrict__ lng, const float* __restrict__ lnb)
{
    extern __shared__ __align__(16) char sm[];
    if (blockIdx.x < 6)
        gemm_core<128, 2, __half>(sm, xh, wq, q16, MROWS, CC, CC,
                                  blockIdx.x, blockIdx.y,
                                  nullptr, rt, qscale, CC, nullptr, nullptr);
    else
        gemm_core<64, 3, __half>(sm, xh, wdn, ckvh, MROWS, RR, CC,
                                 0, blockIdx.y,
                                 nullptr, nullptr, 0.f, 0, lng, lnb);
}

#define GEMM_SMEM (2 * 128 * 112 + 2 * 32 * 272)   // 46080

// ---------------------------------------------------------------------------
// Causal flash attention: 256 threads, 8 warps x 16 q-rows.
// 5-stage KV cp.async ring, prefetch-first, ONE barrier/tile, cpwait2 slack.
// l via MMA on all-ones V pad, fp16x2 exp.
// ---------------------------------------------------------------------------
#define KVBYTES (64 * 144)
#define QBYTES  (128 * 144)
#define NSTG    5
#define ASMEM   (QBYTES + 2 * NSTG * KVBYTES)   // 110592

__global__ __launch_bounds__(256, 2) void attn_f16(
    const __half* __restrict__ q, const __half* __restrict__ kv, __half* __restrict__ ao)
{
    extern __shared__ __align__(16) char sm[];
    const unsigned uQ = sptr(sm);
    const unsigned uK = uQ + QBYTES;
    const unsigned uV = uK + NSTG * KVBYTES;

    const int tid  = threadIdx.x;
    const int lane = tid & 31;
    const int w    = tid >> 5;
    const int g    = lane >> 2;
    const int tig  = lane & 3;
    const int qi   = (gridDim.x - 1) - blockIdx.x;
    const int i0   = qi * 128;
    const int h    = blockIdx.y;
    const int b    = blockIdx.z;
    const int rb   = w * 16;
    const int row_min = i0 + rb;
    const int row_max = row_min + 15;

    // Q fill (warp-local rows)
    {
        const int r  = tid >> 1;
        const int hh = (tid & 1) * 32;
        const uint4* src = (const uint4*)(q + (size_t)(b * TT + i0 + r) * CC + h * DD + hh);
        char* dst = sm + r * 144 + hh * 2;
        uint4 v0 = src[0], v1 = src[1], v2 = src[2], v3 = src[3];
        *(uint4*)dst = v0; *(uint4*)(dst + 16) = v1;
        *(uint4*)(dst + 32) = v2; *(uint4*)(dst + 48) = v3;
    }
    // V pad columns = 1.0h in all NSTG stages (cp.async never writes 128..143)
    for (int s = tid; s < NSTG * 64; s += 256) {
        const int stg = s >> 6;
        const int r   = s & 63;
        *(uint4*)(sm + QBYTES + (NSTG + stg) * KVBYTES + r * 144 + 128) =
            make_uint4(0x3C003C00u, 0x3C003C00u, 0x3C003C00u, 0x3C003C00u);
    }
    __syncwarp();

    unsigned qa[4][4];
    {
        const unsigned aQ = uQ + (rb + (lane & 15)) * 144 + ((lane >> 4) << 4);
#pragma unroll
        for (int kc = 0; kc < 4; ++kc) ldsm4(qa[kc], aQ + kc * 32);
    }

    // KV prefetch mapping
    const int fr = tid >> 2;
    const int fc = (tid & 3) * 2;
    const size_t kvrow0 = (size_t)(b * TT) * KVW + h * DD + fc * 8;

    const int ntile = 2 * qi + 2;
    // prologue: prefetch tiles 0 and 1 into stages 0, 1
    {
        const __half* ks = kv + kvrow0 + (size_t)fr * KVW;
        const unsigned kd = uK + fr * 144 + fc * 16;
        cpa16(kd, ks); cpa16(kd + 16, ks + 8);
        const unsigned vd = uV + fr * 144 + fc * 16;
        cpa16(vd, ks + HH * DD); cpa16(vd + 16, ks + HH * DD + 8);
        cpcommit();
        const __half* ks1 = kv + kvrow0 + (size_t)(64 + fr) * KVW;
        const unsigned kd1 = uK + KVBYTES + fr * 144 + fc * 16;
        cpa16(kd1, ks1); cpa16(kd1 + 16, ks1 + 8);
        const unsigned vd1 = uV + KVBYTES + fr * 144 + fc * 16;
        cpa16(vd1, ks1 + HH * DD); cpa16(vd1 + 16, ks1 + HH * DD + 8);
        cpcommit();
    }

    float mr0 = -INFINITY, mr1 = -INFINITY;
    float oacc[8][4], osum[4];
#pragma unroll
    for (int nt = 0; nt < 8; ++nt)
#pragma unroll
        for (int i = 0; i < 4; ++i) oacc[nt][i] = 0.f;
#pragma unroll
    for (int i = 0; i < 4; ++i) osum[i] = 0.f;

    int cst = 0, pst = 2;
    for (int jt = 0; jt < ntile; ++jt) {
        // prefetch FIRST (stage (jt+2)%5; slowest reader is (jt-1)%5, dist 3)
        const bool pf = (jt + 2 < ntile);
        if (pf) {
            const __half* ks = kv + kvrow0 + (size_t)((jt + 2) * 64 + fr) * KVW;
            const unsigned kd = uK + pst * KVBYTES + fr * 144 + fc * 16;
            cpa16(kd, ks); cpa16(kd + 16, ks + 8);
            const unsigned vd = uV + pst * KVBYTES + fr * 144 + fc * 16;
            cpa16(vd, ks + HH * DD); cpa16(vd + 16, ks + HH * DD + 8);
            cpcommit();
            pst = (pst == NSTG - 1) ? 0 : pst + 1;
        }
        // wait for tile jt's group (pending allowed = #committed-ahead)
        if (pf) cpwait2();
        else if (jt + 1 < ntile) cpwait1();
        else cpwait0();
        __syncthreads();

        const int j0 = jt * 64;
        if (j0 <= row_max) {
            // --- S = Q K^T ---
            float sacc[8][4];
#pragma unroll
            for (int nt = 0; nt < 8; ++nt)
#pragma unroll
                for (int i = 0; i < 4; ++i) sacc[nt][i] = 0.f;

            const unsigned aK = uK + cst * KVBYTES
                              + ((lane & 7) + ((lane & 16) >> 1)) * 144 + ((lane & 8) << 1);
#pragma unroll
            for (int kc = 0; kc < 4; ++kc) {
#pragma unroll
                for (int np = 0; np < 4; ++np) {
                    unsigned bf[4];
                    ldsm4(bf, aK + np * 16 * 144 + kc * 32);
                    mma16(sacc[2 * np],     qa[kc], bf[0], bf[1]);
                    mma16(sacc[2 * np + 1], qa[kc], bf[2], bf[3]);
                }
            }

            // --- causal mask (partial tile only) ---
            if (j0 + 63 > row_min) {
                const int r0g = row_min + g, r1g = r0g + 8;
#pragma unroll
                for (int nt = 0; nt < 8; ++nt) {
                    const int c = j0 + nt * 8 + 2 * tig;
                    if (c > r0g)     sacc[nt][0] = -INFINITY;
                    if (c + 1 > r0g) sacc[nt][1] = -INFINITY;
                    if (c > r1g)     sacc[nt][2] = -INFINITY;
                    if (c + 1 > r1g) sacc[nt][3] = -INFINITY;
                }
            }

            // --- online softmax (base 2) ---
            float tm0 = -INFINITY, tm1 = -INFINITY;
#pragma unroll
            for (int nt = 0; nt < 8; ++nt) {
                tm0 = fmaxf(tm0, fmaxf(sacc[nt][0], sacc[nt][1]));
                tm1 = fmaxf(tm1, fmaxf(sacc[nt][2], sacc[nt][3]));
            }
            tm0 = fmaxf(tm0, __shfl_xor_sync(0xffffffffu, tm0, 1));
            tm0 = fmaxf(tm0, __shfl_xor_sync(0xffffffffu, tm0, 2));
            tm1 = fmaxf(tm1, __shfl_xor_sync(0xffffffffu, tm1, 1));
            tm1 = fmaxf(tm1, __shfl_xor_sync(0xffffffffu, tm1, 2));

            const float mn0 = fmaxf(mr0, tm0), mn1 = fmaxf(mr1, tm1);
            const float al0 = exp2f(mr0 - mn0), al1 = exp2f(mr1 - mn1);
            mr0 = mn0; mr1 = mn1;

            unsigned pfr[4][4];
#pragma unroll
            for (int kk = 0; kk < 4; ++kk) {
                pfr[kk][0] = ex2h2(ph2(sacc[2 * kk][0] - mn0,     sacc[2 * kk][1] - mn0));
                pfr[kk][1] = ex2h2(ph2(sacc[2 * kk][2] - mn1,     sacc[2 * kk][3] - mn1));
                pfr[kk][2] = ex2h2(ph2(sacc[2 * kk + 1][0] - mn0, sacc[2 * kk + 1][1] - mn0));
                pfr[kk][3] = ex2h2(ph2(sacc[2 * kk + 1][2] - mn1, sacc[2 * kk + 1][3] - mn1));
            }

#pragma unroll
            for (int nt = 0; nt < 8; ++nt) {
                oacc[nt][0] *= al0; oacc[nt][1] *= al0;
                oacc[nt][2] *= al1; oacc[nt][3] *= al1;
            }
            osum[0] *= al0; osum[1] *= al0;
            osum[2] *= al1; osum[3] *= al1;

            // --- O += P V ; l += P 1 (pad column) ---
            const unsigned aV  = uV + cst * KVBYTES + (lane & 15) * 144 + (lane & 16);
            const unsigned aVs = uV + cst * KVBYTES + (lane & 15) * 144 + 128;
#pragma unroll
            for (int kc = 0; kc < 4; ++kc) {
#pragma unroll
                for (int np = 0; np < 4; ++np) {
                    unsigned bf[4];
                    ldsm4t(bf, aV + kc * 16 * 144 + np * 32);
                    mma16(oacc[2 * np],     pfr[kc], bf[0], bf[1]);
                    mma16(oacc[2 * np + 1], pfr[kc], bf[2], bf[3]);
                }
                unsigned bl[2];
                ldsm2t(bl, aVs + kc * 16 * 144);
                mma16(osum, pfr[kc], bl[0], bl[1]);
            }
        }
        cst = (cst == NSTG - 1) ? 0 : cst + 1;
    }

    const float inv0 = 1.f / osum[0], inv1 = 1.f / osum[2];
    __half* dst0 = ao + (size_t)(b * TT + i0 + rb + g) * CC + h * DD;
    __half* dst1 = dst0 + (size_t)8 * CC;
#pragma unroll
    for (int nt = 0; nt < 8; ++nt) {
        const int c = nt * 8 + 2 * tig;
        *(unsigned*)(dst0 + c) = ph2(oacc[nt][0] * inv0, oacc[nt][1] * inv0);
        *(unsigned*)(dst1 + c) = ph2(oacc[nt][2] * inv1, oacc[nt][3] * inv1);
    }
}

// ---------------------------------------------------------------------------
// Launch (PDL on dependent kernels)
// ---------------------------------------------------------------------------
extern "C" void kernel_launch(void* const* d_in, const int* in_sizes, int n_in,
                              void* d_out, int out_size)
{
    const float* x     = (const float*)d_in[0];
    const float* Wq    = (const float*)d_in[1];
    const float* Wdown = (const float*)d_in[2];
    const float* ln_g  = (const float*)d_in[3];
    const float* ln_b  = (const float*)d_in[4];
    const float* Wup   = (const float*)d_in[5];
    const float* Wo    = (const float*)d_in[6];
    const float* bo    = (const float*)d_in[7];
    float* out = (float*)d_out;

    void *pxh, *pq, *pckvh, *pkv, *pao, *pwq, *pwdn, *pwup, *pwo, *prt;
    cudaGetSymbolAddress(&pxh,  g_xh);
    cudaGetSymbolAddress(&pq,   g_q16);
    cudaGetSymbolAddress(&pckvh,g_ckvh);
    cudaGetSymbolAddress(&pkv,  g_kv16);
    cudaGetSymbolAddress(&pao,  g_ao16);
    cudaGetSymbolAddress(&pwq,  g_wq);
    cudaGetSymbolAddress(&pwdn, g_wdn);
    cudaGetSymbolAddress(&pwup, g_wup);
    cudaGetSymbolAddress(&pwo,  g_wo);
    cudaGetSymbolAddress(&prt,  g_rt);
    __half* xh   = (__half*)pxh;
    __half* q16  = (__half*)pq;
    __half* ckvh = (__half*)pckvh;
    __half* kv16 = (__half*)pkv;
    __half* ao16 = (__half*)pao;
    __half* wq   = (__half*)pwq;
    __half* wdn  = (__half*)pwdn;
    __half* wup  = (__half*)pwup;
    __half* wo   = (__half*)pwo;
    float2* rt   = (float2*)prt;

    cudaFuncSetAttribute(attn_f16, cudaFuncAttributeMaxDynamicSharedMemorySize, ASMEM);

    cudaLaunchAttribute pdl[1];
    pdl[0].id = cudaLaunchAttributeProgrammaticStreamSerialization;
    pdl[0].val.programmaticStreamSerializationAllowed = 1;

    // 0) conversions + rope table
    f2h_all<<<C5 / 256, 256>>>(x, Wq, Wdown, Wup, Wo, xh, wq, wdn, wup, wo, rt);

    // 1) fused: q = rope(x@Wq)*SCALE*log2e  AND  ckv = layernorm(x@Wdown)
    {
        cudaLaunchConfig_t cfg = {};
        cfg.gridDim = dim3(7, MROWS / 128); cfg.blockDim = dim3(256);
        cfg.dynamicSmemBytes = GEMM_SMEM;
        cfg.attrs = pdl; cfg.numAttrs = 1;
        float qscale = SCALE * LOG2E;
        cudaLaunchKernelEx(&cfg, qdown_k,
            (const __half*)xh, (const __half*)wq, (const __half*)wdn,
            q16, ckvh, (const float2*)rt, qscale, ln_g, ln_b);
    }

    // 2) kv = ckv @ Wup, rope on K half
    {
        cudaLaunchConfig_t cfg = {};
        cfg.gridDim = dim3(KVW / 128, MROWS / 128); cfg.blockDim = dim3(256);
        cfg.dynamicSmemBytes = GEMM_SMEM;
        cfg.attrs = pdl; cfg.numAttrs = 1;
        float one = 1.0f; int lim = HH * DD;
        cudaLaunchKernelEx(&cfg, hgemm16<128, 2, __half>,
            (const __half*)ckvh, (const __half*)wup, kv16,
            (int)MROWS, (int)KVW, (int)RR,
            (const float*)nullptr, (const float2*)rt, one, lim,
            (const float*)nullptr, (const float*)nullptr);
    }

    // 3) attention (5-stage ring, prefetch-first, cpwait2 slack)
    {
        cudaLaunchConfig_t cfg = {};
        cfg.gridDim = dim3(TT / 128, HH, BB); cfg.blockDim = dim3(256);
        cfg.dynamicSmemBytes = ASMEM;
        cfg.attrs = pdl; cfg.numAttrs = 1;
        cudaLaunchKernelEx(&cfg, attn_f16,
            (const __half*)q16, (const __half*)kv16, ao16);
    }

    // 4) out = ao @ Wo + bo
    {
        cudaLaunchConfig_t cfg = {};
        cfg.gridDim = dim3(CC / 128, MROWS / 128); cfg.blockDim = dim3(256);
        cfg.dynamicSmemBytes = GEMM_SMEM;
        cfg.attrs = pdl; cfg.numAttrs = 1;
        float zero = 0.f; int zlim = 0;
        cudaLaunchKernelEx(&cfg, hgemm16<128, 1, float>,
            (const __half*)ao16, (const __half*)wo, out,
            (int)MROWS, (int)CC, (int)CC,
            bo, (const float2*)nullptr, zero, zlim,
            (const float*)nullptr, (const float*)nullptr);
    }
}

// round 16
// speedup vs baseline: 1.1081x; 1.0236x over previous
#include <cuda_runtime.h>
#include <cuda_fp16.h>
#include <math.h>
#include <float.h>

// ---------------------------------------------------------------------------
// MLA forward, fp16 dataflow, fused epilogues, PDL.
// GEMMs: 2-stage, 1 barrier/iter. Attention: 5-stage KV ring, prefetch-first,
// packed-fp16 softmax, constant ones-fragment for l.
//   B=4, T=2048, C=768, H=12, D=64, R=64
// ---------------------------------------------------------------------------

#define BB 4
#define TT 2048
#define CC 768
#define HH 12
#define DD 64
#define RR 64
#define MROWS (BB * TT)            // 8192
#define KVW (2 * HH * DD)          // 1536
#define SCALE 0.125f
#define LOG2E 1.4426950408889634f

// Scratch (device globals)
__device__ __half g_xh  [MROWS * CC];
__device__ __half g_q16 [MROWS * CC];
__device__ __half g_ckvh[MROWS * RR];
__device__ __half g_kv16[MROWS * KVW];
__device__ __half g_ao16[MROWS * CC];
__device__ __half g_wq  [CC * HH * DD];
__device__ __half g_wdn [CC * RR];
__device__ __half g_wup [RR * KVW];
__device__ __half g_wo  [HH * DD * CC];
__device__ float2 g_rt  [TT * 32];       // rope cos/sin table

// ---------------------------------------------------------------------------
// helpers
// ---------------------------------------------------------------------------
__device__ __forceinline__ unsigned ph2(float lo, float hi) {
    __half2 h = __floats2half2_rn(lo, hi);
    return *(unsigned*)&h;
}

__device__ __forceinline__ unsigned ex2h2(unsigned x) {
    unsigned r;
    asm("ex2.approx.f16x2 %0, %1;" : "=r"(r) : "r"(x));
    return r;
}

__device__ __forceinline__ unsigned hmax2(unsigned a, unsigned b) {
    unsigned r;
    asm("max.f16x2 %0, %1, %2;" : "=r"(r) : "r"(a), "r"(b));
    return r;
}

__device__ __forceinline__ unsigned hsub2(unsigned a, unsigned b) {
    unsigned r;
    asm("sub.f16x2 %0, %1, %2;" : "=r"(r) : "r"(a), "r"(b));
    return r;
}

__device__ __forceinline__ void mma16(float* c, const unsigned* a, unsigned b0, unsigned b1) {
    asm volatile(
        "mma.sync.aligned.m16n8k16.row.col.f32.f16.f16.f32 "
        "{%0,%1,%2,%3},{%4,%5,%6,%7},{%8,%9},{%0,%1,%2,%3};"
        : "+f"(c[0]), "+f"(c[1]), "+f"(c[2]), "+f"(c[3])
        : "r"(a[0]), "r"(a[1]), "r"(a[2]), "r"(a[3]), "r"(b0), "r"(b1));
}

__device__ __forceinline__ void ldsm4(unsigned* r, unsigned addr) {
    asm volatile("ldmatrix.sync.aligned.m8n8.x4.shared.b16 {%0,%1,%2,%3},[%4];"
                 : "=r"(r[0]), "=r"(r[1]), "=r"(r[2]), "=r"(r[3]) : "r"(addr));
}
__device__ __forceinline__ void ldsm4t(unsigned* r, unsigned addr) {
    asm volatile("ldmatrix.sync.aligned.m8n8.x4.trans.shared.b16 {%0,%1,%2,%3},[%4];"
                 : "=r"(r[0]), "=r"(r[1]), "=r"(r[2]), "=r"(r[3]) : "r"(addr));
}

__device__ __forceinline__ void cpa16(unsigned dst, const void* src) {
    asm volatile("cp.async.cg.shared.global [%0],[%1],16;" :: "r"(dst), "l"(src));
}
__device__ __forceinline__ void cpcommit() { asm volatile("cp.async.commit_group;"); }
__device__ __forceinline__ void cpwait0()  { asm volatile("cp.async.wait_group 0;"); }
__device__ __forceinline__ void cpwait1()  { asm volatile("cp.async.wait_group 1;"); }
__device__ __forceinline__ void cpwait2()  { asm volatile("cp.async.wait_group 2;"); }

__device__ __forceinline__ unsigned sptr(const void* p) {
    return (unsigned)__cvta_generic_to_shared(p);
}

// ---------------------------------------------------------------------------
// merged fp32->fp16 conversions + rope table (one launch)
// ---------------------------------------------------------------------------
__device__ __forceinline__ void conv8(const float* s, __half* d) {
    float4 v0 = *(const float4*)s;
    float4 v1 = *(const float4*)(s + 4);
    uint4 o = make_uint4(ph2(v0.x, v0.y), ph2(v0.z, v0.w),
                         ph2(v1.x, v1.y), ph2(v1.z, v1.w));
    *(uint4*)d = o;
}

#define C0 (MROWS * CC / 8)
#define C1 (C0 + CC * HH * DD / 8)
#define C2 (C1 + CC * RR / 8)
#define C3 (C2 + RR * KVW / 8)
#define C4 (C3 + HH * DD * CC / 8)
#define C5 (C4 + TT * 32)

__global__ __launch_bounds__(256) void f2h_all(
    const float* __restrict__ x,  const float* __restrict__ wq,
    const float* __restrict__ wdn,const float* __restrict__ wup,
    const float* __restrict__ wo,
    __half* __restrict__ xh, __half* __restrict__ hq, __half* __restrict__ hdn,
    __half* __restrict__ hup, __half* __restrict__ ho, float2* __restrict__ tab)
{
    int i = blockIdx.x * 256 + threadIdx.x;
    if      (i < C0) { int k = i * 8;            conv8(x + k,   xh + k); }
    else if (i < C1) { int k = (i - C0) * 8;     conv8(wq + k,  hq + k); }
    else if (i < C2) { int k = (i - C1) * 8;     conv8(wdn + k, hdn + k); }
    else if (i < C3) { int k = (i - C2) * 8;     conv8(wup + k, hup + k); }
    else if (i < C4) { int k = (i - C3) * 8;     conv8(wo + k,  ho + k); }
    else if (i < C5) {
        int k = i - C4;
        int d = k & 31, t = k >> 5;
        float inv = exp2f(-(float)d * (13.287712379549449f / 32.f));
        float sn, cs;
        sincosf((float)t * inv, &sn, &cs);
        tab[k] = make_float2(cs, sn);
    }
}

// ---------------------------------------------------------------------------
// GEMM core (2-stage cp.async, ONE barrier per k-iter).
//   EPI 1: fp32 out + bias; EPI 2: fp16 out + RoPE; EPI 3: fp16 out + LN(64)
// ---------------------------------------------------------------------------
template<int BN, int EPI, typename OutT>
__device__ __forceinline__ void gemm_core(char* smem,
    const __half* __restrict__ A, const __half* __restrict__ B,
    OutT* __restrict__ C, int M, int N, int K, int bx, int by,
    const float* __restrict__ bias,
    const float2* __restrict__ rt, float ropeScale, int ropeLimit,
    const float* __restrict__ lng, const float* __restrict__ lnb)
{
    constexpr int NT = BN / 16;
    constexpr int ASTR = 112;
    constexpr int BSTR = (BN == 128) ? 272 : 144;
    constexpr int ASTAGE = 128 * ASTR;
    constexpr int BSTAGE = 32 * BSTR;

    const unsigned uA = sptr(smem);
    const unsigned uB = uA + 2 * ASTAGE;

    const int tid  = threadIdx.x;
    const int lane = tid & 31;
    const int w    = tid >> 5;
    const int g    = lane >> 2;
    const int tig  = lane & 3;
    const int wm   = (w & 3) * 32;
    const int wn   = (w >> 2) * (BN / 2);
    const int m0   = by * 128;
    const int n0   = bx * BN;

    const int far = tid >> 1;
    const int fac = (tid & 1) * 2;
    const int fbk = tid >> 3;
    const int fbc = (BN == 128) ? (tid & 7) * 2 : (tid & 7);

    const __half* Asrc = A + (size_t)(m0 + far) * K + fac * 8;
    const __half* Bsrc = B + (size_t)fbk * N + n0 + fbc * 8;
    const unsigned adst = uA + far * ASTR + fac * 16;
    const unsigned bdst = uB + fbk * BSTR + fbc * 16;

    float acc[2][NT][4];
#pragma unroll
    for (int mt = 0; mt < 2; ++mt)
#pragma unroll
        for (int nt = 0; nt < NT; ++nt)
#pragma unroll
            for (int i = 0; i < 4; ++i) acc[mt][nt][i] = 0.f;

    const int niters = K >> 5;

    // prologue: prefetch tile 0
    cpa16(adst, Asrc); cpa16(adst + 16, Asrc + 8);
    cpa16(bdst, Bsrc);
    if (BN == 128) cpa16(bdst + 16, Bsrc + 8);
    cpcommit();

    for (int it = 0; it < niters; ++it) {
        cpwait0();
        __syncthreads();
        if (it + 1 < niters) {
            const int st = (it + 1) & 1;
            const __half* as = Asrc + (it + 1) * 32;
            const __half* bs = Bsrc + (size_t)(it + 1) * 32 * N;
            cpa16(adst + st * ASTAGE, as); cpa16(adst + st * ASTAGE + 16, as + 8);
            cpa16(bdst + st * BSTAGE, bs);
            if (BN == 128) cpa16(bdst + st * BSTAGE + 16, bs + 8);
            cpcommit();
        }

        const int st = it & 1;
        const unsigned aAb = uA + st * ASTAGE + (wm + (lane & 15)) * ASTR + ((lane >> 4) << 4);
        unsigned af[2][2][4];
#pragma unroll
        for (int kc = 0; kc < 2; ++kc)
#pragma unroll
            for (int mt = 0; mt < 2; ++mt)
                ldsm4(af[kc][mt], aAb + mt * 16 * ASTR + kc * 32);

        const unsigned aBb = uB + st * BSTAGE + (lane & 15) * BSTR
                           + (wn + ((lane >> 4) << 3)) * 2;
#pragma unroll
        for (int kc = 0; kc < 2; ++kc) {
#pragma unroll
            for (int np = 0; np < NT / 2; ++np) {
                unsigned bf[4];
                ldsm4t(bf, aBb + kc * 16 * BSTR + np * 32);
                mma16(acc[0][2 * np],     af[kc][0], bf[0], bf[1]);
                mma16(acc[1][2 * np],     af[kc][1], bf[0], bf[1]);
                mma16(acc[0][2 * np + 1], af[kc][0], bf[2], bf[3]);
                mma16(acc[1][2 * np + 1], af[kc][1], bf[2], bf[3]);
            }
        }
    }

    // ------------------------- epilogues -------------------------
    if constexpr (EPI == 1) {
#pragma unroll
        for (int mt = 0; mt < 2; ++mt) {
            const int r0 = m0 + wm + mt * 16 + g;
#pragma unroll
            for (int nt = 0; nt < NT; ++nt) {
                const int c0 = n0 + wn + nt * 8 + 2 * tig;
                const float b0 = bias[c0], b1 = bias[c0 + 1];
                *(float2*)((float*)C + (size_t)r0 * N + c0) =
                    make_float2(acc[mt][nt][0] + b0, acc[mt][nt][1] + b1);
                *(float2*)((float*)C + (size_t)(r0 + 8) * N + c0) =
                    make_float2(acc[mt][nt][2] + b0, acc[mt][nt][3] + b1);
            }
        }
    } else if constexpr (EPI == 2) {
        const bool doRope = (n0 + wn) < ropeLimit;
        __half* Ch = (__half*)C;
#pragma unroll
        for (int mt = 0; mt < 2; ++mt) {
            const int r0 = m0 + wm + mt * 16 + g;
            const int t0 = r0 & (TT - 1);
#pragma unroll
            for (int ntp = 0; ntp < 4; ++ntp) {
                const int clo = n0 + wn + ntp * 8 + 2 * tig;
                float lo0[2], hi0[2], lo1[2], hi1[2];
                if (doRope) {
#pragma unroll
                    for (int j = 0; j < 2; ++j) {
                        const int d = ntp * 8 + 2 * tig + j;
                        const float2 cs0 = rt[t0 * 32 + d];
                        const float2 cs1 = rt[(t0 + 8) * 32 + d];
                        const float xl0 = acc[mt][ntp][j],     xh0 = acc[mt][ntp + 4][j];
                        const float xl1 = acc[mt][ntp][j + 2], xh1 = acc[mt][ntp + 4][j + 2];
                        lo0[j] = xl0 * cs0.x - xh0 * cs0.y;
                        hi0[j] = xh0 * cs0.x + xl0 * cs0.y;
                        lo1[j] = xl1 * cs1.x - xh1 * cs1.y;
                        hi1[j] = xh1 * cs1.x + xl1 * cs1.y;
                    }
                } else {
#pragma unroll
                    for (int j = 0; j < 2; ++j) {
                        lo0[j] = acc[mt][ntp][j];     hi0[j] = acc[mt][ntp + 4][j];
                        lo1[j] = acc[mt][ntp][j + 2]; hi1[j] = acc[mt][ntp + 4][j + 2];
                    }
                }
                const float s = ropeScale;
                *(unsigned*)(Ch + (size_t)r0 * N + clo)        = ph2(lo0[0] * s, lo0[1] * s);
                *(unsigned*)(Ch + (size_t)r0 * N + clo + 32)   = ph2(hi0[0] * s, hi0[1] * s);
                *(unsigned*)(Ch + (size_t)(r0 + 8) * N + clo)      = ph2(lo1[0] * s, lo1[1] * s);
                *(unsigned*)(Ch + (size_t)(r0 + 8) * N + clo + 32) = ph2(hi1[0] * s, hi1[1] * s);
            }
        }
    } else if constexpr (EPI == 3) {
        __syncthreads();               // smem overlay: all ldsm of last tile done
        float2* red = (float2*)smem;
        float rs[2][2], rq[2][2];
#pragma unroll
        for (int mt = 0; mt < 2; ++mt)
#pragma unroll
            for (int hh = 0; hh < 2; ++hh) {
                float s = 0.f, sq = 0.f;
#pragma unroll
                for (int nt = 0; nt < NT; ++nt)
#pragma unroll
                    for (int j = 0; j < 2; ++j) {
                        float v = acc[mt][nt][2 * hh + j];
                        s += v; sq += v * v;
                    }
                s  += __shfl_xor_sync(0xffffffffu, s, 1);
                s  += __shfl_xor_sync(0xffffffffu, s, 2);
                sq += __shfl_xor_sync(0xffffffffu, sq, 1);
                sq += __shfl_xor_sync(0xffffffffu, sq, 2);
                rs[mt][hh] = s; rq[mt][hh] = sq;
            }
        if (tig == 0) {
#pragma unroll
            for (int mt = 0; mt < 2; ++mt)
#pragma unroll
                for (int hh = 0; hh < 2; ++hh) {
                    const int rl = wm + mt * 16 + g + hh * 8;
                    red[(w >> 2) * 128 + rl] = make_float2(rs[mt][hh], rq[mt][hh]);
                }
        }
        __syncthreads();
        __half* Ch = (__half*)C;
#pragma unroll
        for (int mt = 0; mt < 2; ++mt)
#pragma unroll
            for (int hh = 0; hh < 2; ++hh) {
                const int rl = wm + mt * 16 + g + hh * 8;
                const float2 a = red[rl], bb = red[128 + rl];
                const float mean = (a.x + bb.x) * (1.f / 64.f);
                const float var  = (a.y + bb.y) * (1.f / 64.f) - mean * mean;
                const float inv  = rsqrtf(var + 1e-5f);
                const int r0 = m0 + rl;
#pragma unroll
                for (int nt = 0; nt < NT; ++nt) {
                    const int c = wn + nt * 8 + 2 * tig;
                    const float v0 = (acc[mt][nt][2 * hh]     - mean) * inv * lng[c]     + lnb[c];
                    const float v1 = (acc[mt][nt][2 * hh + 1] - mean) * inv * lng[c + 1] + lnb[c + 1];
                    *(unsigned*)(Ch + (size_t)r0 * N + c) = ph2(v0, v1);
                }
            }
    }
}

// standalone GEMM wrapper
template<int BN, int EPI, typename OutT>
__global__ __launch_bounds__(256) void hgemm16(
    const __half* __restrict__ A, const __half* __restrict__ B,
    OutT* __restrict__ C, int M, int N, int K,
    const float* __restrict__ bias,
    const float2* __restrict__ rt, float ropeScale, int ropeLimit,
    const float* __restrict__ lng, const float* __restrict__ lnb)
{
    extern __shared__ __align__(16) char sm[];
    gemm_core<BN, EPI, OutT>(sm, A, B, C, M, N, K, blockIdx.x, blockIdx.y,
                             bias, rt, ropeScale, ropeLimit, lng, lnb);
}

// fused Wq (RoPE) + Wdown (LayerNorm): gridDim.x = 7
__global__ __launch_bounds__(256) void qdown_k(
    const __half* __restrict__ xh, const __half* __restrict__ wq,
    const __half* __restrict__ wdn, __half* __restrict__ q16,
    __half* __restrict__ ckvh, const float2* __restrict__ rt, float qscale,
    const float* __restrict__ lng, const float* __restrict__ lnb)
{
    extern __shared__ __align__(16) char sm[];
    if (blockIdx.x < 6)
        gemm_core<128, 2, __half>(sm, xh, wq, q16, MROWS, CC, CC,
                                  blockIdx.x, blockIdx.y,
                                  nullptr, rt, qscale, CC, nullptr, nullptr);
    else
        gemm_core<64, 3, __half>(sm, xh, wdn, ckvh, MROWS, RR, CC,
                                 0, blockIdx.y,
                                 nullptr, nullptr, 0.f, 0, lng, lnb);
}

#define GEMM_SMEM (2 * 128 * 112 + 2 * 32 * 272)   // 46080

// ---------------------------------------------------------------------------
// Causal flash attention: 256 threads, 8 warps x 16 q-rows.
// 5-stage KV cp.async ring, prefetch-first, ONE barrier/tile, cpwait2 slack.
// Packed-fp16 softmax; l via MMA against constant all-ones fragment.
// ---------------------------------------------------------------------------
#define KVBYTES (64 * 144)
#define QBYTES  (128 * 144)
#define NSTG    5
#define ASMEM   (QBYTES + 2 * NSTG * KVBYTES)   // 110592
#define ONESF   0x3C003C00u

__global__ __launch_bounds__(256, 2) void attn_f16(
    const __half* __restrict__ q, const __half* __restrict__ kv, __half* __restrict__ ao)
{
    extern __shared__ __align__(16) char sm[];
    const unsigned uQ = sptr(sm);
    const unsigned uK = uQ + QBYTES;
    const unsigned uV = uK + NSTG * KVBYTES;

    const int tid  = threadIdx.x;
    const int lane = tid & 31;
    const int w    = tid >> 5;
    const int g    = lane >> 2;
    const int tig  = lane & 3;
    const int qi   = (gridDim.x - 1) - blockIdx.x;
    const int i0   = qi * 128;
    const int h    = blockIdx.y;
    const int b    = blockIdx.z;
    const int rb   = w * 16;
    const int row_min = i0 + rb;
    const int row_max = row_min + 15;

    // Q fill (warp-local rows)
    {
        const int r  = tid >> 1;
        const int hh = (tid & 1) * 32;
        const uint4* src = (const uint4*)(q + (size_t)(b * TT + i0 + r) * CC + h * DD + hh);
        char* dst = sm + r * 144 + hh * 2;
        uint4 v0 = src[0], v1 = src[1], v2 = src[2], v3 = src[3];
        *(uint4*)dst = v0; *(uint4*)(dst + 16) = v1;
        *(uint4*)(dst + 32) = v2; *(uint4*)(dst + 48) = v3;
    }
    __syncwarp();

    unsigned qa[4][4];
    {
        const unsigned aQ = uQ + (rb + (lane & 15)) * 144 + ((lane >> 4) << 4);
#pragma unroll
        for (int kc = 0; kc < 4; ++kc) ldsm4(qa[kc], aQ + kc * 32);
    }

    // KV prefetch mapping
    const int fr = tid >> 2;
    const int fc = (tid & 3) * 2;
    const size_t kvrow0 = (size_t)(b * TT) * KVW + h * DD + fc * 8;

    const int ntile = 2 * qi + 2;
    // prologue: prefetch tiles 0 and 1 into stages 0, 1
    {
        const __half* ks = kv + kvrow0 + (size_t)fr * KVW;
        const unsigned kd = uK + fr * 144 + fc * 16;
        cpa16(kd, ks); cpa16(kd + 16, ks + 8);
        const unsigned vd = uV + fr * 144 + fc * 16;
        cpa16(vd, ks + HH * DD); cpa16(vd + 16, ks + HH * DD + 8);
        cpcommit();
        const __half* ks1 = kv + kvrow0 + (size_t)(64 + fr) * KVW;
        const unsigned kd1 = uK + KVBYTES + fr * 144 + fc * 16;
        cpa16(kd1, ks1); cpa16(kd1 + 16, ks1 + 8);
        const unsigned vd1 = uV + KVBYTES + fr * 144 + fc * 16;
        cpa16(vd1, ks1 + HH * DD); cpa16(vd1 + 16, ks1 + HH * DD + 8);
        cpcommit();
    }

    float mr0 = -INFINITY, mr1 = -INFINITY;
    float oacc[8][4], osum[4];
#pragma unroll
    for (int nt = 0; nt < 8; ++nt)
#pragma unroll
        for (int i = 0; i < 4; ++i) oacc[nt][i] = 0.f;
#pragma unroll
    for (int i = 0; i < 4; ++i) osum[i] = 0.f;

    int cst = 0, pst = 2;
    for (int jt = 0; jt < ntile; ++jt) {
        // prefetch FIRST (stage (jt+2)%5; slowest reader is (jt-1)%5, dist 3)
        const bool pf = (jt + 2 < ntile);
        if (pf) {
            const __half* ks = kv + kvrow0 + (size_t)((jt + 2) * 64 + fr) * KVW;
            const unsigned kd = uK + pst * KVBYTES + fr * 144 + fc * 16;
            cpa16(kd, ks); cpa16(kd + 16, ks + 8);
            const unsigned vd = uV + pst * KVBYTES + fr * 144 + fc * 16;
            cpa16(vd, ks + HH * DD); cpa16(vd + 16, ks + HH * DD + 8);
            cpcommit();
            pst = (pst == NSTG - 1) ? 0 : pst + 1;
        }
        if (pf) cpwait2();
        else if (jt + 1 < ntile) cpwait1();
        else cpwait0();
        __syncthreads();

        const int j0 = jt * 64;
        if (j0 <= row_max) {
            // --- S = Q K^T ---
            float sacc[8][4];
#pragma unroll
            for (int nt = 0; nt < 8; ++nt)
#pragma unroll
                for (int i = 0; i < 4; ++i) sacc[nt][i] = 0.f;

            const unsigned aK = uK + cst * KVBYTES
                              + ((lane & 7) + ((lane & 16) >> 1)) * 144 + ((lane & 8) << 1);
#pragma unroll
            for (int kc = 0; kc < 4; ++kc) {
#pragma unroll
                for (int np = 0; np < 4; ++np) {
                    unsigned bf[4];
                    ldsm4(bf, aK + np * 16 * 144 + kc * 32);
                    mma16(sacc[2 * np],     qa[kc], bf[0], bf[1]);
                    mma16(sacc[2 * np + 1], qa[kc], bf[2], bf[3]);
                }
            }

            // --- causal mask (partial tile only) ---
            if (j0 + 63 > row_min) {
                const int r0g = row_min + g, r1g = r0g + 8;
#pragma unroll
                for (int nt = 0; nt < 8; ++nt) {
                    const int c = j0 + nt * 8 + 2 * tig;
                    if (c > r0g)     sacc[nt][0] = -INFINITY;
                    if (c + 1 > r0g) sacc[nt][1] = -INFINITY;
                    if (c > r1g)     sacc[nt][2] = -INFINITY;
                    if (c + 1 > r1g) sacc[nt][3] = -INFINITY;
                }
            }

            // --- pack scores to fp16x2: w0 = rows g, w1 = rows g+8 ---
            unsigned w0[8], w1[8];
#pragma unroll
            for (int nt = 0; nt < 8; ++nt) {
                w0[nt] = ph2(sacc[nt][0], sacc[nt][1]);
                w1[nt] = ph2(sacc[nt][2], sacc[nt][3]);
            }

            // --- packed max reduce ---
            unsigned a0 = hmax2(hmax2(hmax2(w0[0], w0[1]), hmax2(w0[2], w0[3])),
                                hmax2(hmax2(w0[4], w0[5]), hmax2(w0[6], w0[7])));
            unsigned a1 = hmax2(hmax2(hmax2(w1[0], w1[1]), hmax2(w1[2], w1[3])),
                                hmax2(hmax2(w1[4], w1[5]), hmax2(w1[6], w1[7])));
            a0 = hmax2(a0, __shfl_xor_sync(0xffffffffu, a0, 1));
            a0 = hmax2(a0, __shfl_xor_sync(0xffffffffu, a0, 2));
            a1 = hmax2(a1, __shfl_xor_sync(0xffffffffu, a1, 1));
            a1 = hmax2(a1, __shfl_xor_sync(0xffffffffu, a1, 2));
            __half2 h0 = *(__half2*)&a0, h1 = *(__half2*)&a1;
            const float tm0 = fmaxf(__low2float(h0), __high2float(h0));
            const float tm1 = fmaxf(__low2float(h1), __high2float(h1));

            const float mn0 = fmaxf(mr0, tm0), mn1 = fmaxf(mr1, tm1);
            const float al0 = exp2f(mr0 - mn0), al1 = exp2f(mr1 - mn1);
            mr0 = mn0; mr1 = mn1;
            const unsigned m0h = ph2(mn0, mn0), m1h = ph2(mn1, mn1);

            // --- P = 2^(s - m) in packed fp16 ---
            unsigned pfr[4][4];
#pragma unroll
            for (int kk = 0; kk < 4; ++kk) {
                pfr[kk][0] = ex2h2(hsub2(w0[2 * kk],     m0h));
                pfr[kk][1] = ex2h2(hsub2(w1[2 * kk],     m1h));
                pfr[kk][2] = ex2h2(hsub2(w0[2 * kk + 1], m0h));
                pfr[kk][3] = ex2h2(hsub2(w1[2 * kk + 1], m1h));
            }

#pragma unroll
            for (int nt = 0; nt < 8; ++nt) {
                oacc[nt][0] *= al0; oacc[nt][1] *= al0;
                oacc[nt][2] *= al1; oacc[nt][3] *= al1;
            }
            osum[0] *= al0; osum[1] *= al0;
            osum[2] *= al1; osum[3] *= al1;

            // --- O += P V ; l += P 1 (constant ones fragment) ---
            const unsigned aV = uV + cst * KVBYTES + (lane & 15) * 144 + (lane & 16);
#pragma unroll
            for (int kc = 0; kc < 4; ++kc) {
#pragma unroll
                for (int np = 0; np < 4; ++np) {
                    unsigned bf[4];
                    ldsm4t(bf, aV + kc * 16 * 144 + np * 32);
                    mma16(oacc[2 * np],     pfr[kc], bf[0], bf[1]);
                    mma16(oacc[2 * np + 1], pfr[kc], bf[2], bf[3]);
                }
                mma16(osum, pfr[kc], ONESF, ONESF);
            }
        }
        cst = (cst == NSTG - 1) ? 0 : cst + 1;
    }

    const float inv0 = 1.f / osum[0], inv1 = 1.f / osum[2];
    __half* dst0 = ao + (size_t)(b * TT + i0 + rb + g) * CC + h * DD;
    __half* dst1 = dst0 + (size_t)8 * CC;
#pragma unroll
    for (int nt = 0; nt < 8; ++nt) {
        const int c = nt * 8 + 2 * tig;
        *(unsigned*)(dst0 + c) = ph2(oacc[nt][0] * inv0, oacc[nt][1] * inv0);
        *(unsigned*)(dst1 + c) = ph2(oacc[nt][2] * inv1, oacc[nt][3] * inv1);
    }
}

// ---------------------------------------------------------------------------
// Launch (PDL on dependent kernels)
// ---------------------------------------------------------------------------
extern "C" void kernel_launch(void* const* d_in, const int* in_sizes, int n_in,
                              void* d_out, int out_size)
{
    const float* x     = (const float*)d_in[0];
    const float* Wq    = (const float*)d_in[1];
    const float* Wdown = (const float*)d_in[2];
    const float* ln_g  = (const float*)d_in[3];
    const float* ln_b  = (const float*)d_in[4];
    const float* Wup   = (const float*)d_in[5];
    const float* Wo    = (const float*)d_in[6];
    const float* bo    = (const float*)d_in[7];
    float* out = (float*)d_out;

    void *pxh, *pq, *pckvh, *pkv, *pao, *pwq, *pwdn, *pwup, *pwo, *prt;
    cudaGetSymbolAddress(&pxh,  g_xh);
    cudaGetSymbolAddress(&pq,   g_q16);
    cudaGetSymbolAddress(&pckvh,g_ckvh);
    cudaGetSymbolAddress(&pkv,  g_kv16);
    cudaGetSymbolAddress(&pao,  g_ao16);
    cudaGetSymbolAddress(&pwq,  g_wq);
    cudaGetSymbolAddress(&pwdn, g_wdn);
    cudaGetSymbolAddress(&pwup, g_wup);
    cudaGetSymbolAddress(&pwo,  g_wo);
    cudaGetSymbolAddress(&prt,  g_rt);
    __half* xh   = (__half*)pxh;
    __half* q16  = (__half*)pq;
    __half* ckvh = (__half*)pckvh;
    __half* kv16 = (__half*)pkv;
    __half* ao16 = (__half*)pao;
    __half* wq   = (__half*)pwq;
    __half* wdn  = (__half*)pwdn;
    __half* wup  = (__half*)pwup;
    __half* wo   = (__half*)pwo;
    float2* rt   = (float2*)prt;

    cudaFuncSetAttribute(attn_f16, cudaFuncAttributeMaxDynamicSharedMemorySize, ASMEM);

    cudaLaunchAttribute pdl[1];
    pdl[0].id = cudaLaunchAttributeProgrammaticStreamSerialization;
    pdl[0].val.programmaticStreamSerializationAllowed = 1;

    // 0) conversions + rope table
    f2h_all<<<C5 / 256, 256>>>(x, Wq, Wdown, Wup, Wo, xh, wq, wdn, wup, wo, rt);

    // 1) fused: q = rope(x@Wq)*SCALE*log2e  AND  ckv = layernorm(x@Wdown)
    {
        cudaLaunchConfig_t cfg = {};
        cfg.gridDim = dim3(7, MROWS / 128); cfg.blockDim = dim3(256);
        cfg.dynamicSmemBytes = GEMM_SMEM;
        cfg.attrs = pdl; cfg.numAttrs = 1;
        float qscale = SCALE * LOG2E;
        cudaLaunchKernelEx(&cfg, qdown_k,
            (const __half*)xh, (const __half*)wq, (const __half*)wdn,
            q16, ckvh, (const float2*)rt, qscale, ln_g, ln_b);
    }

    // 2) kv = ckv @ Wup, rope on K half
    {
        cudaLaunchConfig_t cfg = {};
        cfg.gridDim = dim3(KVW / 128, MROWS / 128); cfg.blockDim = dim3(256);
        cfg.dynamicSmemBytes = GEMM_SMEM;
        cfg.attrs = pdl; cfg.numAttrs = 1;
        float one = 1.0f; int lim = HH * DD;
        cudaLaunchKernelEx(&cfg, hgemm16<128, 2, __half>,
            (const __half*)ckvh, (const __half*)wup, kv16,
            (int)MROWS, (int)KVW, (int)RR,
            (const float*)nullptr, (const float2*)rt, one, lim,
            (const float*)nullptr, (const float*)nullptr);
    }

    // 3) attention
    {
        cudaLaunchConfig_t cfg = {};
        cfg.gridDim = dim3(TT / 128, HH, BB); cfg.blockDim = dim3(256);
        cfg.dynamicSmemBytes = ASMEM;
        cfg.attrs = pdl; cfg.numAttrs = 1;
        cudaLaunchKernelEx(&cfg, attn_f16,
            (const __half*)q16, (const __half*)kv16, ao16);
    }

    // 4) out = ao @ Wo + bo
    {
        cudaLaunchConfig_t cfg = {};
        cfg.gridDim = dim3(CC / 128, MROWS / 128); cfg.blockDim = dim3(256);
        cfg.dynamicSmemBytes = GEMM_SMEM;
        cfg.attrs = pdl; cfg.numAttrs = 1;
        float zero = 0.f; int zlim = 0;
        cudaLaunchKernelEx(&cfg, hgemm16<128, 1, float>,
            (const __half*)ao16, (const __half*)wo, out,
            (int)MROWS, (int)CC, (int)CC,
            bo, (const float2*)nullptr, zero, zlim,
            (const float*)nullptr, (const float*)nullptr);
    }
}